// round 9
// baseline (speedup 1.0000x reference)
#include <cuda_runtime.h>
#include <math.h>

#define MAX_N    131072
#define NGRAPH   256
#define MAXSEG   1024
#define PSPLIT   4
#define NBINS    2048
#define CHUNKB   8       // bins per thread (2048/256)

// Scratch (static __device__ arrays — no allocation allowed)
__device__ float d_p[MAX_N];        // x[i] . w_rel
__device__ float d_r[MAX_N];        // x[i] . w_root
__device__ float d_s[MAX_N];        // segment-summed p over edges
__device__ float d_score[MAX_N];    // fallback scratch only
__device__ float d_w[MAX_N];        // dense weight: score/k if kept else 0
__device__ int   d_starts[NGRAPH + 1];

__device__ __forceinline__ unsigned score_key(float s) {
    unsigned u = __float_as_uint(s);
    return (u & 0x80000000u) ? ~u : (u | 0x80000000u);   // monotone
}
__device__ __forceinline__ float key_score(unsigned k) {
    return (k & 0x80000000u) ? __uint_as_float(k & 0x7fffffffu)
                             : __uint_as_float(~k);
}
__device__ __forceinline__ int lower_bound_i(const int* a, int n, int v) {
    int lo = 0, hi = n;
    while (lo < hi) {
        int mid = (lo + hi) >> 1;
        if (a[mid] < v) lo = mid + 1; else hi = mid;
    }
    return lo;
}
__device__ __forceinline__ float dot4(float4 a, float4 b) {
    return a.x * b.x + a.y * b.y + a.z * b.z + a.w * b.w;
}

// ---------------------------------------------------------------------------
// K0: per-node dots p = x.w_rel, r = x.w_root ; zero s ; zero out.
// ---------------------------------------------------------------------------
__global__ void k_node_dots(const float* __restrict__ x,
                            const float* __restrict__ w_rel,
                            const float* __restrict__ w_root,
                            float* __restrict__ out,
                            int N) {
    int gid = blockIdx.x * blockDim.x + threadIdx.x;
    if (gid < NGRAPH * 64) out[gid] = 0.0f;
    int node = gid >> 3;
    if (node >= N) return;
    int sub = gid & 7;
    const float4* xr = (const float4*)(x + (size_t)node * 64);
    float4 v0 = xr[sub];
    float4 v1 = xr[sub + 8];
    const float4* wrv = (const float4*)w_rel;
    const float4* wtv = (const float4*)w_root;
    float a = dot4(v0, wrv[sub]) + dot4(v1, wrv[sub + 8]);
    float b = dot4(v0, wtv[sub]) + dot4(v1, wtv[sub + 8]);
#pragma unroll
    for (int o = 4; o; o >>= 1) {
        a += __shfl_xor_sync(0xffffffffu, a, o);
        b += __shfl_xor_sync(0xffffffffu, b, o);
    }
    if (sub == 0) {
        d_p[node] = a;
        d_r[node] = b;
        d_s[node] = 0.0f;
    }
}

// ---------------------------------------------------------------------------
// K1: edge scatter  s[dst] += p[src].  8 edges/thread for MLP.
// ---------------------------------------------------------------------------
__global__ void k_edge_scatter8(const int* __restrict__ ei, int E) {
    int t = blockIdx.x * blockDim.x + threadIdx.x;
    int E8 = E >> 3;
    if (t >= E8) return;
    const int4* sv = (const int4*)ei;
    const int4* dv = (const int4*)(ei + E);
    int4 sa = sv[2 * t], sb = sv[2 * t + 1];
    int4 da = dv[2 * t], db = dv[2 * t + 1];
    float p0 = d_p[sa.x], p1 = d_p[sa.y], p2 = d_p[sa.z], p3 = d_p[sa.w];
    float p4 = d_p[sb.x], p5 = d_p[sb.y], p6 = d_p[sb.z], p7 = d_p[sb.w];
    atomicAdd(&d_s[da.x], p0);
    atomicAdd(&d_s[da.y], p1);
    atomicAdd(&d_s[da.z], p2);
    atomicAdd(&d_s[da.w], p3);
    atomicAdd(&d_s[db.x], p4);
    atomicAdd(&d_s[db.y], p5);
    atomicAdd(&d_s[db.z], p6);
    atomicAdd(&d_s[db.w], p7);
}
__global__ void k_edge_scatter_tail(const int* __restrict__ ei, int base, int E) {
    int t = base + blockIdx.x * blockDim.x + threadIdx.x;
    if (t < E) atomicAdd(&d_s[ei[E + t]], d_p[ei[t]]);
}

// ---------------------------------------------------------------------------
// K2: per-graph fused score+select (histogram top-k, exact lexsort ties).
// Writes dense d_w (score/k for kept, 0 for dropped) and d_starts.
// ---------------------------------------------------------------------------
__global__ void k_rank(const int* __restrict__ batch,
                       const float* __restrict__ b_rel,
                       int N) {
    __shared__ unsigned keys[MAXSEG];
    __shared__ unsigned hist[NBINS];
    __shared__ unsigned chsum[256];
    __shared__ unsigned suf[256];
    __shared__ int s_se[2];
    __shared__ int s_bin, s_m1, s_ncand;
    __shared__ int cand_idx[MAXSEG];
    __shared__ unsigned cand_key[MAXSEG];

    int g = blockIdx.x;
    int t = threadIdx.x;

    if (t < 2) s_se[t] = lower_bound_i(batch, N, g + t);
    if (t == 0) { s_bin = -1; s_m1 = 0; s_ncand = 0; }
#pragma unroll
    for (int b = 0; b < CHUNKB; ++b) hist[t * CHUNKB + b] = 0;
    __syncthreads();

    int start = s_se[0];
    int end   = s_se[1];
    int n = end - start;
    if (t == 0) d_starts[g] = start;
    if (t == 1 && g == NGRAPH - 1) d_starts[NGRAPH] = end;

    int k = (n + 1) >> 1;
    float invk = 1.0f / fmaxf((float)k, 1.0f);
    float bias = b_rel[0];

    if (n > MAXSEG) {
        for (int i = t; i < n; i += 256)
            d_score[start + i] = tanhf(d_s[start + i] + bias + d_r[start + i]);
        __syncthreads();
        for (int i = t; i < n; i += 256) {
            float si = d_score[start + i];
            int cnt = 0;
            for (int j = 0; j < i; ++j)     cnt += (d_score[start + j] >= si);
            for (int j = i + 1; j < n; ++j) cnt += (d_score[start + j] >  si);
            d_w[start + i] = (cnt < k) ? si * invk : 0.0f;
        }
        return;
    }

    for (int i = t; i < n; i += 256) {
        float sc = tanhf(d_s[start + i] + bias + d_r[start + i]);
        unsigned key = score_key(sc);
        keys[i] = key;
        atomicAdd(&hist[key >> 21], 1u);
    }
    __syncthreads();

    unsigned cs = 0;
#pragma unroll
    for (int b = 0; b < CHUNKB; ++b) cs += hist[t * CHUNKB + b];
    chsum[t] = cs;
    __syncthreads();

    // single-warp suffix scan over 256 chunk sums
    if (t < 32) {
        unsigned v[8];
        unsigned tot = 0;
#pragma unroll
        for (int j = 7; j >= 0; --j) {
            tot += chsum[t * 8 + j];
            v[j] = tot;
        }
        unsigned run = tot;
#pragma unroll
        for (int off = 1; off < 32; off <<= 1) {
            unsigned q = __shfl_down_sync(0xffffffffu, run, off);
            if (t + off < 32) run += q;
        }
        unsigned tail = run - tot;
#pragma unroll
        for (int j = 0; j < 8; ++j) suf[t * 8 + j] = v[j] + tail;
    }
    __syncthreads();

    {
        unsigned above = suf[t] - chsum[t];
        if ((int)above < k && k <= (int)suf[t]) {
            int acc = (int)above;
            for (int b = CHUNKB - 1; b >= 0; --b) {
                int h = (int)hist[t * CHUNKB + b];
                if (acc < k && k <= acc + h) { s_bin = t * CHUNKB + b; s_m1 = acc; }
                acc += h;
            }
        }
    }
    __syncthreads();

    int binb = s_bin, m1 = s_m1;
    for (int i = t; i < n; i += 256) {
        unsigned key = keys[i];
        int bin = (int)(key >> 21);
        if (bin > binb) {
            d_w[start + i] = key_score(key) * invk;
        } else if (bin < binb) {
            d_w[start + i] = 0.0f;
        } else {
            int c = atomicAdd(&s_ncand, 1);
            cand_idx[c] = i;
            cand_key[c] = key;
        }
    }
    __syncthreads();

    int r = k - m1;
    int nc = s_ncand;
    for (int c = t; c < nc; c += 256) {
        unsigned ki = cand_key[c];
        int ii = cand_idx[c];
        int cnt = 0;
        for (int j = 0; j < nc; ++j) {
            unsigned kj = cand_key[j];
            cnt += (kj > ki) || (kj == ki && cand_idx[j] < ii);
        }
        d_w[start + ii] = (cnt < r) ? key_score(ki) * invk : 0.0f;
    }
}

// ---------------------------------------------------------------------------
// K3: pooling. Dense branch-free stream: acc += w * x[row] unconditionally
// (w = 0 for dropped rows). Sequential, coalesced, no dependent addressing.
// ---------------------------------------------------------------------------
__global__ void k_pool(const float* __restrict__ x,
                       float* __restrict__ out) {
    __shared__ float ps[16][64];

    int g  = blockIdx.x >> 2;
    int sp = blockIdx.x & 3;
    int start = d_starts[g];
    int n = d_starts[g + 1] - start;
    int chunk = (n + PSPLIT - 1) / PSPLIT;
    int r0 = start + sp * chunk;
    int r1 = r0 + chunk; { int lim = start + n; if (r1 > lim) r1 = lim; }
    int t = threadIdx.x;
    int q  = t & 15;        // col quad
    int rg = t >> 4;        // row group (16)

    const float4* xv = (const float4*)x;
    float4 acc = make_float4(0.f, 0.f, 0.f, 0.f);

#pragma unroll 8
    for (int row = r0 + rg; row < r1; row += 16) {
        float w  = __ldg(&d_w[row]);
        float4 v = xv[(size_t)row * 16 + q];
        acc.x += w * v.x; acc.y += w * v.y;
        acc.z += w * v.z; acc.w += w * v.w;
    }

    ps[rg][q * 4 + 0] = acc.x;
    ps[rg][q * 4 + 1] = acc.y;
    ps[rg][q * 4 + 2] = acc.z;
    ps[rg][q * 4 + 3] = acc.w;
    __syncthreads();
    if (t < 64) {
        float v = 0.0f;
#pragma unroll
        for (int j = 0; j < 16; ++j) v += ps[j][t];
        if (v != 0.0f) atomicAdd(&out[g * 64 + t], v);
    }
}

// ---------------------------------------------------------------------------
extern "C" void kernel_launch(void* const* d_in, const int* in_sizes, int n_in,
                              void* d_out, int out_size) {
    const float* x      = (const float*)d_in[0];
    const int*   ei     = (const int*)d_in[1];
    const int*   batch  = (const int*)d_in[2];
    const float* w_rel  = (const float*)d_in[3];
    const float* b_rel  = (const float*)d_in[4];
    const float* w_root = (const float*)d_in[5];
    float*       out    = (float*)d_out;

    int N = in_sizes[2];
    int E = in_sizes[1] / 2;

    {
        long long threads = (long long)N * 8;
        int blocks = (int)((threads + 255) / 256);
        k_node_dots<<<blocks, 256>>>(x, w_rel, w_root, out, N);
    }
    {
        int E8 = E >> 3;
        if (E8 > 0)
            k_edge_scatter8<<<(E8 + 255) / 256, 256>>>(ei, E);
        int rem = E - (E8 << 3);
        if (rem > 0)
            k_edge_scatter_tail<<<(rem + 255) / 256, 256>>>(ei, E8 << 3, E);
    }
    k_rank<<<NGRAPH, 256>>>(batch, b_rel, N);
    k_pool<<<NGRAPH * PSPLIT, 256>>>(x, out);
}

// round 10
// speedup vs baseline: 1.0414x; 1.0414x over previous
#include <cuda_runtime.h>
#include <math.h>

#define MAX_N    131072
#define NGRAPH   256
#define MAXSEG   1024
#define NBINS    2048
#define CHUNKB   8       // bins per thread (2048/256)

// Scratch (static __device__ arrays — no allocation allowed)
__device__ float d_p[MAX_N];        // x[i] . w_rel
__device__ float d_r[MAX_N];        // x[i] . w_root
__device__ float d_s[MAX_N];        // segment-summed p over edges
__device__ float d_score[MAX_N];    // fallback scratch only
__device__ float d_w[MAX_N];        // fallback scratch only

__device__ __forceinline__ unsigned score_key(float s) {
    unsigned u = __float_as_uint(s);
    return (u & 0x80000000u) ? ~u : (u | 0x80000000u);   // monotone
}
__device__ __forceinline__ float key_score(unsigned k) {
    return (k & 0x80000000u) ? __uint_as_float(k & 0x7fffffffu)
                             : __uint_as_float(~k);
}
__device__ __forceinline__ int lower_bound_i(const int* a, int n, int v) {
    int lo = 0, hi = n;
    while (lo < hi) {
        int mid = (lo + hi) >> 1;
        if (a[mid] < v) lo = mid + 1; else hi = mid;
    }
    return lo;
}
__device__ __forceinline__ float dot4(float4 a, float4 b) {
    return a.x * b.x + a.y * b.y + a.z * b.z + a.w * b.w;
}

// ---------------------------------------------------------------------------
// K0: per-node dots p = x.w_rel, r = x.w_root ; zero s.
// ---------------------------------------------------------------------------
__global__ void k_node_dots(const float* __restrict__ x,
                            const float* __restrict__ w_rel,
                            const float* __restrict__ w_root,
                            int N) {
    int gid = blockIdx.x * blockDim.x + threadIdx.x;
    int node = gid >> 3;
    if (node >= N) return;
    int sub = gid & 7;
    const float4* xr = (const float4*)(x + (size_t)node * 64);
    float4 v0 = xr[sub];
    float4 v1 = xr[sub + 8];
    const float4* wrv = (const float4*)w_rel;
    const float4* wtv = (const float4*)w_root;
    float a = dot4(v0, wrv[sub]) + dot4(v1, wrv[sub + 8]);
    float b = dot4(v0, wtv[sub]) + dot4(v1, wtv[sub + 8]);
#pragma unroll
    for (int o = 4; o; o >>= 1) {
        a += __shfl_xor_sync(0xffffffffu, a, o);
        b += __shfl_xor_sync(0xffffffffu, b, o);
    }
    if (sub == 0) {
        d_p[node] = a;
        d_r[node] = b;
        d_s[node] = 0.0f;
    }
}

// ---------------------------------------------------------------------------
// K1: edge scatter  s[dst] += p[src].  8 edges/thread; tail folded in.
// ---------------------------------------------------------------------------
__global__ void k_edge_scatter(const int* __restrict__ ei, int E) {
    int t = blockIdx.x * blockDim.x + threadIdx.x;
    int E8 = E >> 3;
    if (t < E8) {
        const int4* sv = (const int4*)ei;
        const int4* dv = (const int4*)(ei + E);
        int4 sa = sv[2 * t], sb = sv[2 * t + 1];
        int4 da = dv[2 * t], db = dv[2 * t + 1];
        float p0 = d_p[sa.x], p1 = d_p[sa.y], p2 = d_p[sa.z], p3 = d_p[sa.w];
        float p4 = d_p[sb.x], p5 = d_p[sb.y], p6 = d_p[sb.z], p7 = d_p[sb.w];
        atomicAdd(&d_s[da.x], p0);
        atomicAdd(&d_s[da.y], p1);
        atomicAdd(&d_s[da.z], p2);
        atomicAdd(&d_s[da.w], p3);
        atomicAdd(&d_s[db.x], p4);
        atomicAdd(&d_s[db.y], p5);
        atomicAdd(&d_s[db.z], p6);
        atomicAdd(&d_s[db.w], p7);
    }
    int base = E8 << 3;
    int rem = E - base;
    if (t < rem) {
        atomicAdd(&d_s[ei[E + base + t]], d_p[ei[base + t]]);
    }
}

// ---------------------------------------------------------------------------
// K2: fused per-graph score + histogram top-k select + weighted mean pool.
// One block per graph; weights live in smem; direct store to out (no atomics).
// Exact lexsort tie semantics (score desc, index asc).
// ---------------------------------------------------------------------------
__global__ void k_rank_pool(const float* __restrict__ x,
                            const int* __restrict__ batch,
                            const float* __restrict__ b_rel,
                            float* __restrict__ out,
                            int N) {
    __shared__ unsigned hist[NBINS];
    __shared__ float    sw[MAXSEG];
    __shared__ unsigned chsum[256];
    __shared__ unsigned suf[256];
    __shared__ int s_se[2];
    __shared__ int s_bin, s_m1, s_ncand;
    __shared__ int      cand_idx[MAXSEG];
    __shared__ unsigned cand_key[MAXSEG];
    __shared__ float ps[16][64];

    int g = blockIdx.x;
    int t = threadIdx.x;

    if (t < 2) s_se[t] = lower_bound_i(batch, N, g + t);
    if (t == 0) { s_bin = -1; s_m1 = 0; s_ncand = 0; }
#pragma unroll
    for (int b = 0; b < CHUNKB; ++b) hist[t * CHUNKB + b] = 0;
    __syncthreads();

    int start = s_se[0];
    int end   = s_se[1];
    int n = end - start;
    int k = (n + 1) >> 1;
    float invk = 1.0f / fmaxf((float)k, 1.0f);
    float bias = b_rel[0];

    if (n <= MAXSEG) {
        // ---- phase 1: keys + histogram (keys stashed in cand_key slot order i)
        for (int i = t; i < n; i += 256) {
            float sc = tanhf(d_s[start + i] + bias + d_r[start + i]);
            unsigned key = score_key(sc);
            cand_key[i] = key;           // temporary: keys by position
            atomicAdd(&hist[key >> 21], 1u);
        }
        __syncthreads();

        unsigned cs = 0;
#pragma unroll
        for (int b = 0; b < CHUNKB; ++b) cs += hist[t * CHUNKB + b];
        chsum[t] = cs;
        __syncthreads();

        // single-warp suffix scan over 256 chunk sums
        if (t < 32) {
            unsigned v[8];
            unsigned tot = 0;
#pragma unroll
            for (int j = 7; j >= 0; --j) {
                tot += chsum[t * 8 + j];
                v[j] = tot;
            }
            unsigned run = tot;
#pragma unroll
            for (int off = 1; off < 32; off <<= 1) {
                unsigned q = __shfl_down_sync(0xffffffffu, run, off);
                if (t + off < 32) run += q;
            }
            unsigned tail = run - tot;
#pragma unroll
            for (int j = 0; j < 8; ++j) suf[t * 8 + j] = v[j] + tail;
        }
        __syncthreads();

        {
            unsigned above = suf[t] - chsum[t];
            if ((int)above < k && k <= (int)suf[t]) {
                int acc = (int)above;
                for (int b = CHUNKB - 1; b >= 0; --b) {
                    int h = (int)hist[t * CHUNKB + b];
                    if (acc < k && k <= acc + h) { s_bin = t * CHUNKB + b; s_m1 = acc; }
                    acc += h;
                }
            }
        }
        __syncthreads();

        int binb = s_bin, m1 = s_m1;
        // ---- phase 2: classify into sw (threshold bin -> candidate list)
        for (int i = t; i < n; i += 256) {
            unsigned key = cand_key[i];
            int bin = (int)(key >> 21);
            if (bin > binb) {
                sw[i] = key_score(key) * invk;
            } else if (bin < binb) {
                sw[i] = 0.0f;
            } else {
                int c = atomicAdd(&s_ncand, 1);
                cand_idx[c] = i;
            }
        }
        __syncthreads();
        // compact candidate keys (cand_key currently holds keys-by-position)
        int nc = s_ncand;
        unsigned mykey[4];
        int myidx[4];
        int mycnt = 0;
        for (int c = t; c < nc; c += 256) {
            myidx[mycnt] = cand_idx[c];
            mykey[mycnt] = cand_key[cand_idx[c]];
            ++mycnt;
        }
        __syncthreads();
        for (int c = t, m = 0; c < nc; c += 256, ++m) cand_key[c] = mykey[m];
        __syncthreads();

        int r = k - m1;
        for (int c = t, m = 0; c < nc; c += 256, ++m) {
            unsigned ki = mykey[m];
            int ii = myidx[m];
            int cnt = 0;
            for (int j = 0; j < nc; ++j) {
                unsigned kj = cand_key[j];
                cnt += (kj > ki) || (kj == ki && cand_idx[j] < ii);
            }
            sw[ii] = (cnt < r) ? key_score(ki) * invk : 0.0f;
        }
        __syncthreads();

        // ---- phase 3: pool (dense branch-free stream, weights from smem)
        int q  = t & 15;
        int rg = t >> 4;
        const float4* xv = (const float4*)x;
        float4 acc = make_float4(0.f, 0.f, 0.f, 0.f);
#pragma unroll 4
        for (int i = rg; i < n; i += 16) {
            float w  = sw[i];
            float4 v = xv[(size_t)(start + i) * 16 + q];
            acc.x += w * v.x; acc.y += w * v.y;
            acc.z += w * v.z; acc.w += w * v.w;
        }
        ps[rg][q * 4 + 0] = acc.x;
        ps[rg][q * 4 + 1] = acc.y;
        ps[rg][q * 4 + 2] = acc.z;
        ps[rg][q * 4 + 3] = acc.w;
        __syncthreads();
        if (t < 64) {
            float v = 0.0f;
#pragma unroll
            for (int j = 0; j < 16; ++j) v += ps[j][t];
            out[g * 64 + t] = v;
        }
    } else {
        // ---- improbable fallback: global O(n^2) + pool from d_w
        for (int i = t; i < n; i += 256)
            d_score[start + i] = tanhf(d_s[start + i] + bias + d_r[start + i]);
        __syncthreads();
        for (int i = t; i < n; i += 256) {
            float si = d_score[start + i];
            int cnt = 0;
            for (int j = 0; j < i; ++j)     cnt += (d_score[start + j] >= si);
            for (int j = i + 1; j < n; ++j) cnt += (d_score[start + j] >  si);
            d_w[start + i] = (cnt < k) ? si * invk : 0.0f;
        }
        __syncthreads();
        int q  = t & 15;
        int rg = t >> 4;
        const float4* xv = (const float4*)x;
        float4 acc = make_float4(0.f, 0.f, 0.f, 0.f);
        for (int i = rg; i < n; i += 16) {
            float w  = d_w[start + i];
            float4 v = xv[(size_t)(start + i) * 16 + q];
            acc.x += w * v.x; acc.y += w * v.y;
            acc.z += w * v.z; acc.w += w * v.w;
        }
        ps[rg][q * 4 + 0] = acc.x;
        ps[rg][q * 4 + 1] = acc.y;
        ps[rg][q * 4 + 2] = acc.z;
        ps[rg][q * 4 + 3] = acc.w;
        __syncthreads();
        if (t < 64) {
            float v = 0.0f;
#pragma unroll
            for (int j = 0; j < 16; ++j) v += ps[j][t];
            out[g * 64 + t] = v;
        }
    }
}

// ---------------------------------------------------------------------------
extern "C" void kernel_launch(void* const* d_in, const int* in_sizes, int n_in,
                              void* d_out, int out_size) {
    const float* x      = (const float*)d_in[0];
    const int*   ei     = (const int*)d_in[1];
    const int*   batch  = (const int*)d_in[2];
    const float* w_rel  = (const float*)d_in[3];
    const float* b_rel  = (const float*)d_in[4];
    const float* w_root = (const float*)d_in[5];
    float*       out    = (float*)d_out;

    int N = in_sizes[2];
    int E = in_sizes[1] / 2;

    {
        long long threads = (long long)N * 8;
        int blocks = (int)((threads + 255) / 256);
        k_node_dots<<<blocks, 256>>>(x, w_rel, w_root, N);
    }
    {
        int E8 = E >> 3;
        int work = E8 > 8 ? E8 : 8;     // cover tail even when E8 == 0
        k_edge_scatter<<<(work + 255) / 256, 256>>>(ei, E);
    }
    k_rank_pool<<<NGRAPH, 256>>>(x, batch, b_rel, out, N);
}

// round 11
// speedup vs baseline: 1.0604x; 1.0183x over previous
#include <cuda_runtime.h>
#include <math.h>

#define MAX_N    131072
#define NGRAPH   256
#define MAXSEG   1024
#define NBINS    2048
#define RPT      512     // rank_pool threads
#define CHUNKB   4       // bins per thread (2048/512)

// Scratch (static __device__ arrays — no allocation allowed)
__device__ float d_p[MAX_N];        // x[i] . w_rel
__device__ float d_r[MAX_N];        // x[i] . w_root
__device__ float d_s[MAX_N];        // segment-summed p over edges
__device__ float d_score[MAX_N];    // fallback scratch only
__device__ float d_w[MAX_N];        // fallback scratch only

__device__ __forceinline__ unsigned score_key(float s) {
    unsigned u = __float_as_uint(s);
    return (u & 0x80000000u) ? ~u : (u | 0x80000000u);   // monotone
}
__device__ __forceinline__ float key_score(unsigned k) {
    return (k & 0x80000000u) ? __uint_as_float(k & 0x7fffffffu)
                             : __uint_as_float(~k);
}
__device__ __forceinline__ int lower_bound_i(const int* a, int n, int v) {
    int lo = 0, hi = n;
    while (lo < hi) {
        int mid = (lo + hi) >> 1;
        if (a[mid] < v) lo = mid + 1; else hi = mid;
    }
    return lo;
}
__device__ __forceinline__ float dot4(float4 a, float4 b) {
    return a.x * b.x + a.y * b.y + a.z * b.z + a.w * b.w;
}

// ---------------------------------------------------------------------------
// K0: per-node dots. 4 threads/node, 4x float4 per thread (high MLP).
// ---------------------------------------------------------------------------
__global__ void k_node_dots(const float* __restrict__ x,
                            const float* __restrict__ w_rel,
                            const float* __restrict__ w_root,
                            int N) {
    int gid = blockIdx.x * blockDim.x + threadIdx.x;
    int node = gid >> 2;
    if (node >= N) return;
    int sub = gid & 3;
    const float4* xr = (const float4*)(x + (size_t)node * 64);
    float4 v0 = xr[sub];
    float4 v1 = xr[sub + 4];
    float4 v2 = xr[sub + 8];
    float4 v3 = xr[sub + 12];
    const float4* wrv = (const float4*)w_rel;
    const float4* wtv = (const float4*)w_root;
    float a = dot4(v0, wrv[sub])     + dot4(v1, wrv[sub + 4])
            + dot4(v2, wrv[sub + 8]) + dot4(v3, wrv[sub + 12]);
    float b = dot4(v0, wtv[sub])     + dot4(v1, wtv[sub + 4])
            + dot4(v2, wtv[sub + 8]) + dot4(v3, wtv[sub + 12]);
#pragma unroll
    for (int o = 2; o; o >>= 1) {
        a += __shfl_xor_sync(0xffffffffu, a, o);
        b += __shfl_xor_sync(0xffffffffu, b, o);
    }
    if (sub == 0) {
        d_p[node] = a;
        d_r[node] = b;
        d_s[node] = 0.0f;
    }
}

// ---------------------------------------------------------------------------
// K1: edge scatter  s[dst] += p[src].  8 edges/thread; tail folded in.
// ---------------------------------------------------------------------------
__global__ void k_edge_scatter(const int* __restrict__ ei, int E) {
    int t = blockIdx.x * blockDim.x + threadIdx.x;
    int E8 = E >> 3;
    if (t < E8) {
        const int4* sv = (const int4*)ei;
        const int4* dv = (const int4*)(ei + E);
        int4 sa = sv[2 * t], sb = sv[2 * t + 1];
        int4 da = dv[2 * t], db = dv[2 * t + 1];
        float p0 = d_p[sa.x], p1 = d_p[sa.y], p2 = d_p[sa.z], p3 = d_p[sa.w];
        float p4 = d_p[sb.x], p5 = d_p[sb.y], p6 = d_p[sb.z], p7 = d_p[sb.w];
        atomicAdd(&d_s[da.x], p0);
        atomicAdd(&d_s[da.y], p1);
        atomicAdd(&d_s[da.z], p2);
        atomicAdd(&d_s[da.w], p3);
        atomicAdd(&d_s[db.x], p4);
        atomicAdd(&d_s[db.y], p5);
        atomicAdd(&d_s[db.z], p6);
        atomicAdd(&d_s[db.w], p7);
    }
    int base = E8 << 3;
    int rem = E - base;
    if (t < rem) {
        atomicAdd(&d_s[ei[E + base + t]], d_p[ei[base + t]]);
    }
}

// ---------------------------------------------------------------------------
// K2: fused per-graph score + histogram top-k select + weighted mean pool.
// 512 threads per block, one block per graph. Exact lexsort tie semantics.
// ---------------------------------------------------------------------------
__global__ void __launch_bounds__(RPT)
k_rank_pool(const float* __restrict__ x,
            const int* __restrict__ batch,
            const float* __restrict__ b_rel,
            float* __restrict__ out,
            int N) {
    __shared__ unsigned hist[NBINS];
    __shared__ float    sw[MAXSEG];
    __shared__ unsigned chsum[RPT];
    __shared__ unsigned suf[RPT];
    __shared__ int s_se[2];
    __shared__ int s_bin, s_m1, s_ncand;
    __shared__ int      cand_idx[MAXSEG];
    __shared__ unsigned cand_key[MAXSEG];
    __shared__ float ps[32][64];

    int g = blockIdx.x;
    int t = threadIdx.x;

    if (t < 2) s_se[t] = lower_bound_i(batch, N, g + t);
    if (t == 0) { s_bin = -1; s_m1 = 0; s_ncand = 0; }
#pragma unroll
    for (int b = 0; b < CHUNKB; ++b) hist[t * CHUNKB + b] = 0;
    __syncthreads();

    int start = s_se[0];
    int end   = s_se[1];
    int n = end - start;
    int k = (n + 1) >> 1;
    float invk = 1.0f / fmaxf((float)k, 1.0f);
    float bias = b_rel[0];

    if (n <= MAXSEG) {
        // ---- phase 1: keys + histogram (keys by position in cand_key)
        for (int i = t; i < n; i += RPT) {
            float sc = tanhf(d_s[start + i] + bias + d_r[start + i]);
            unsigned key = score_key(sc);
            cand_key[i] = key;
            atomicAdd(&hist[key >> 21], 1u);
        }
        __syncthreads();

        unsigned cs = 0;
#pragma unroll
        for (int b = 0; b < CHUNKB; ++b) cs += hist[t * CHUNKB + b];
        chsum[t] = cs;
        __syncthreads();

        // single-warp suffix scan over 512 chunk sums (16 per lane)
        if (t < 32) {
            unsigned v[16];
            unsigned tot = 0;
#pragma unroll
            for (int j = 15; j >= 0; --j) {
                tot += chsum[t * 16 + j];
                v[j] = tot;
            }
            unsigned run = tot;
#pragma unroll
            for (int off = 1; off < 32; off <<= 1) {
                unsigned q = __shfl_down_sync(0xffffffffu, run, off);
                if (t + off < 32) run += q;
            }
            unsigned tail = run - tot;
#pragma unroll
            for (int j = 0; j < 16; ++j) suf[t * 16 + j] = v[j] + tail;
        }
        __syncthreads();

        {
            unsigned above = suf[t] - chsum[t];
            if ((int)above < k && k <= (int)suf[t]) {
                int acc = (int)above;
                for (int b = CHUNKB - 1; b >= 0; --b) {
                    int h = (int)hist[t * CHUNKB + b];
                    if (acc < k && k <= acc + h) { s_bin = t * CHUNKB + b; s_m1 = acc; }
                    acc += h;
                }
            }
        }
        __syncthreads();

        int binb = s_bin, m1 = s_m1;
        // ---- phase 2: classify into sw; threshold bin -> candidates
        for (int i = t; i < n; i += RPT) {
            unsigned key = cand_key[i];
            int bin = (int)(key >> 21);
            if (bin > binb) {
                sw[i] = key_score(key) * invk;
            } else if (bin < binb) {
                sw[i] = 0.0f;
            } else {
                int c = atomicAdd(&s_ncand, 1);
                cand_idx[c] = i;
            }
        }
        __syncthreads();
        int nc = s_ncand;
        unsigned mykey[2];
        int myidx[2];
        int mycnt = 0;
        for (int c = t; c < nc; c += RPT) {
            myidx[mycnt] = cand_idx[c];
            mykey[mycnt] = cand_key[cand_idx[c]];
            ++mycnt;
        }
        __syncthreads();
        for (int c = t, m = 0; c < nc; c += RPT, ++m) cand_key[c] = mykey[m];
        __syncthreads();

        int r = k - m1;
        for (int c = t, m = 0; c < nc; c += RPT, ++m) {
            unsigned ki = mykey[m];
            int ii = myidx[m];
            int cnt = 0;
            for (int j = 0; j < nc; ++j) {
                unsigned kj = cand_key[j];
                cnt += (kj > ki) || (kj == ki && cand_idx[j] < ii);
            }
            sw[ii] = (cnt < r) ? key_score(ki) * invk : 0.0f;
        }
        __syncthreads();

        // ---- phase 3: pool (dense branch-free stream, weights from smem)
        int q  = t & 15;        // col quad
        int rg = t >> 4;        // row group (32)
        const float4* xv = (const float4*)x;
        float4 acc = make_float4(0.f, 0.f, 0.f, 0.f);
#pragma unroll 4
        for (int i = rg; i < n; i += 32) {
            float w  = sw[i];
            float4 v = xv[(size_t)(start + i) * 16 + q];
            acc.x += w * v.x; acc.y += w * v.y;
            acc.z += w * v.z; acc.w += w * v.w;
        }
        ps[rg][q * 4 + 0] = acc.x;
        ps[rg][q * 4 + 1] = acc.y;
        ps[rg][q * 4 + 2] = acc.z;
        ps[rg][q * 4 + 3] = acc.w;
        __syncthreads();
        if (t < 64) {
            float v = 0.0f;
#pragma unroll
            for (int j = 0; j < 32; ++j) v += ps[j][t];
            out[g * 64 + t] = v;
        }
    } else {
        // ---- improbable fallback: global O(n^2) + pool from d_w
        for (int i = t; i < n; i += RPT)
            d_score[start + i] = tanhf(d_s[start + i] + bias + d_r[start + i]);
        __syncthreads();
        for (int i = t; i < n; i += RPT) {
            float si = d_score[start + i];
            int cnt = 0;
            for (int j = 0; j < i; ++j)     cnt += (d_score[start + j] >= si);
            for (int j = i + 1; j < n; ++j) cnt += (d_score[start + j] >  si);
            d_w[start + i] = (cnt < k) ? si * invk : 0.0f;
        }
        __syncthreads();
        int q  = t & 15;
        int rg = t >> 4;
        const float4* xv = (const float4*)x;
        float4 acc = make_float4(0.f, 0.f, 0.f, 0.f);
        for (int i = rg; i < n; i += 32) {
            float w  = d_w[start + i];
            float4 v = xv[(size_t)(start + i) * 16 + q];
            acc.x += w * v.x; acc.y += w * v.y;
            acc.z += w * v.z; acc.w += w * v.w;
        }
        ps[rg][q * 4 + 0] = acc.x;
        ps[rg][q * 4 + 1] = acc.y;
        ps[rg][q * 4 + 2] = acc.z;
        ps[rg][q * 4 + 3] = acc.w;
        __syncthreads();
        if (t < 64) {
            float v = 0.0f;
#pragma unroll
            for (int j = 0; j < 32; ++j) v += ps[j][t];
            out[g * 64 + t] = v;
        }
    }
}

// ---------------------------------------------------------------------------
extern "C" void kernel_launch(void* const* d_in, const int* in_sizes, int n_in,
                              void* d_out, int out_size) {
    const float* x      = (const float*)d_in[0];
    const int*   ei     = (const int*)d_in[1];
    const int*   batch  = (const int*)d_in[2];
    const float* w_rel  = (const float*)d_in[3];
    const float* b_rel  = (const float*)d_in[4];
    const float* w_root = (const float*)d_in[5];
    float*       out    = (float*)d_out;

    int N = in_sizes[2];
    int E = in_sizes[1] / 2;

    {
        long long threads = (long long)N * 4;
        int blocks = (int)((threads + 255) / 256);
        k_node_dots<<<blocks, 256>>>(x, w_rel, w_root, N);
    }
    {
        int E8 = E >> 3;
        int work = E8 > 8 ? E8 : 8;     // cover tail even when E8 == 0
        k_edge_scatter<<<(work + 255) / 256, 256>>>(ei, E);
    }
    k_rank_pool<<<NGRAPH, RPT>>>(x, batch, b_rel, out, N);
}